// round 3
// baseline (speedup 1.0000x reference)
#include <cuda_runtime.h>
#include <math.h>

#define NMAX   50000
#define EMAX   1048576
#define EMB    256
#define MID    256
#define OUTD   128
#define SCAN_B 1024
#define NBLK_SCAN ((NMAX + SCAN_B - 1) / SCAN_B)   // 49

// ---- scratch (static device globals; no runtime allocation) ----
__device__ float g_H1[NMAX * MID];     // dis .* (node_emb @ W1)
__device__ float g_A1[NMAX * MID];     // gelu(agg) -> layer-2 input
__device__ float g_H2[NMAX * OUTD];    // dis .* (A1 @ W2)
__device__ float g_dis[NMAX];          // D^-1/2 (in-degree + self loop)
__device__ int   g_deg[NMAX];
__device__ int   g_rowptr[NMAX + 1];
__device__ int   g_cur[NMAX];
__device__ int   g_col[EMAX];
__device__ int   g_blocksum[NBLK_SCAN + 1];

// ----------------------------------------------------------------------------
// degree / normalization
// ----------------------------------------------------------------------------
__global__ void zero_deg_kernel(int n) {
    int i = blockIdx.x * blockDim.x + threadIdx.x;
    if (i < n) g_deg[i] = 0;
}

__global__ void count_deg_kernel(const int* __restrict__ dst, int E) {
    int e = blockIdx.x * blockDim.x + threadIdx.x;
    if (e < E) atomicAdd(&g_deg[dst[e]], 1);
}

__global__ void compute_dis_kernel(int n) {
    int i = blockIdx.x * blockDim.x + threadIdx.x;
    if (i < n) g_dis[i] = rsqrtf((float)(g_deg[i] + 1));  // +1 = self loop
}

// ----------------------------------------------------------------------------
// multi-block exclusive scan of g_deg -> g_rowptr
// ----------------------------------------------------------------------------
__global__ __launch_bounds__(SCAN_B)
void scan_phase1_kernel(int n) {           // per-block exclusive scan + block sum
    __shared__ int s[SCAN_B];
    int i = blockIdx.x * SCAN_B + threadIdx.x;
    int v = (i < n) ? g_deg[i] : 0;
    s[threadIdx.x] = v;
    __syncthreads();
#pragma unroll
    for (int off = 1; off < SCAN_B; off <<= 1) {
        int t = (threadIdx.x >= off) ? s[threadIdx.x - off] : 0;
        __syncthreads();
        s[threadIdx.x] += t;
        __syncthreads();
    }
    if (i < n) g_rowptr[i] = s[threadIdx.x] - v;   // exclusive, no block offset yet
    if (threadIdx.x == SCAN_B - 1) g_blocksum[blockIdx.x] = s[SCAN_B - 1];
}

__global__ __launch_bounds__(64)
void scan_phase2_kernel(int nblk) {        // exclusive scan of block sums (1 block)
    __shared__ int s[64];
    int v = (threadIdx.x < nblk) ? g_blocksum[threadIdx.x] : 0;
    s[threadIdx.x] = v;
    __syncthreads();
#pragma unroll
    for (int off = 1; off < 64; off <<= 1) {
        int t = (threadIdx.x >= off) ? s[threadIdx.x - off] : 0;
        __syncthreads();
        s[threadIdx.x] += t;
        __syncthreads();
    }
    if (threadIdx.x < nblk) g_blocksum[threadIdx.x] = s[threadIdx.x] - v;
    if (threadIdx.x == 63) g_blocksum[nblk] = s[63];   // total
}

__global__ __launch_bounds__(SCAN_B)
void scan_phase3_kernel(int n, int nblk) { // add offsets, init cursors, tail
    int i = blockIdx.x * SCAN_B + threadIdx.x;
    if (i < n) {
        int ex = g_rowptr[i] + g_blocksum[blockIdx.x];
        g_rowptr[i] = ex;
        g_cur[i] = ex;
    }
    if (i == 0) g_rowptr[n] = g_blocksum[nblk];
}

// ----------------------------------------------------------------------------
// CSR fill: g_col[rowptr[d] + k] = src  (unordered within a segment -- fine)
// ----------------------------------------------------------------------------
__global__ void fill_csr_kernel(const int* __restrict__ src,
                                const int* __restrict__ dst, int E) {
    int e = blockIdx.x * blockDim.x + threadIdx.x;
    if (e < E) {
        int d = dst[e];
        int pos = atomicAdd(&g_cur[d], 1);
        g_col[pos] = src[e];
    }
}

// ----------------------------------------------------------------------------
// fp32 SIMT GEMM, 128x128 tile, 8x8 microtile, double-buffered smem.
// C[m,:] = dis[m] * (A @ B)[m,:]
// ----------------------------------------------------------------------------
#define BM 128
#define BN 128
#define BK 16

__global__ __launch_bounds__(256)
void gemm_scale_kernel(const float* __restrict__ A, const float* __restrict__ B,
                       float* __restrict__ C, int M, int N, int K) {
    __shared__ float As[2][BK][BM + 4];
    __shared__ float Bs[2][BK][BN + 4];

    int tid = threadIdx.x;
    int tx = tid & 15;        // 0..15 -> 8 cols each
    int ty = tid >> 4;        // 0..15 -> 8 rows each

    int m0 = blockIdx.y * BM;
    int n0 = blockIdx.x * BN;

    // loader indices
    int aRow = tid >> 1;            // 0..127
    int akk  = (tid & 1) * 8;       // 0 or 8
    int bkk  = tid >> 4;            // 0..15
    int bnn  = (tid & 15) * 8;      // 0..120

    float acc[8][8];
#pragma unroll
    for (int i = 0; i < 8; i++)
#pragma unroll
        for (int j = 0; j < 8; j++) acc[i][j] = 0.0f;

    int nK = K / BK;

    // prefetch regs
    float4 ra0, ra1, rb0, rb1;

    // ---- load tile 0 ----
    {
        int gm = m0 + aRow;
        if (gm < M) {
            const float* ap = A + (size_t)gm * K + akk;
            ra0 = *(const float4*)(ap);
            ra1 = *(const float4*)(ap + 4);
        } else {
            ra0 = ra1 = make_float4(0.f, 0.f, 0.f, 0.f);
        }
        const float* bp = B + (size_t)bkk * N + n0 + bnn;
        rb0 = *(const float4*)(bp);
        rb1 = *(const float4*)(bp + 4);
    }
    // store tile 0
    {
        As[0][akk + 0][aRow] = ra0.x; As[0][akk + 1][aRow] = ra0.y;
        As[0][akk + 2][aRow] = ra0.z; As[0][akk + 3][aRow] = ra0.w;
        As[0][akk + 4][aRow] = ra1.x; As[0][akk + 5][aRow] = ra1.y;
        As[0][akk + 6][aRow] = ra1.z; As[0][akk + 7][aRow] = ra1.w;
        *(float4*)&Bs[0][bkk][bnn]     = rb0;
        *(float4*)&Bs[0][bkk][bnn + 4] = rb1;
    }
    __syncthreads();

    for (int it = 0; it < nK; it++) {
        int buf = it & 1;
        // prefetch next tile into registers
        if (it + 1 < nK) {
            int k0 = (it + 1) * BK;
            int gm = m0 + aRow;
            if (gm < M) {
                const float* ap = A + (size_t)gm * K + k0 + akk;
                ra0 = *(const float4*)(ap);
                ra1 = *(const float4*)(ap + 4);
            } else {
                ra0 = ra1 = make_float4(0.f, 0.f, 0.f, 0.f);
            }
            const float* bp = B + (size_t)(k0 + bkk) * N + n0 + bnn;
            rb0 = *(const float4*)(bp);
            rb1 = *(const float4*)(bp + 4);
        }

        // compute on current buffer
#pragma unroll
        for (int k = 0; k < BK; k++) {
            float4 a0 = *(const float4*)&As[buf][k][ty * 8];
            float4 a1 = *(const float4*)&As[buf][k][ty * 8 + 4];
            float4 b0 = *(const float4*)&Bs[buf][k][tx * 8];
            float4 b1 = *(const float4*)&Bs[buf][k][tx * 8 + 4];
            float ar[8] = {a0.x, a0.y, a0.z, a0.w, a1.x, a1.y, a1.z, a1.w};
            float br[8] = {b0.x, b0.y, b0.z, b0.w, b1.x, b1.y, b1.z, b1.w};
#pragma unroll
            for (int i = 0; i < 8; i++)
#pragma unroll
                for (int j = 0; j < 8; j++)
                    acc[i][j] = fmaf(ar[i], br[j], acc[i][j]);
        }

        // store next tile to the other buffer
        if (it + 1 < nK) {
            int nb = buf ^ 1;
            As[nb][akk + 0][aRow] = ra0.x; As[nb][akk + 1][aRow] = ra0.y;
            As[nb][akk + 2][aRow] = ra0.z; As[nb][akk + 3][aRow] = ra0.w;
            As[nb][akk + 4][aRow] = ra1.x; As[nb][akk + 5][aRow] = ra1.y;
            As[nb][akk + 6][aRow] = ra1.z; As[nb][akk + 7][aRow] = ra1.w;
            *(float4*)&Bs[nb][bkk][bnn]     = rb0;
            *(float4*)&Bs[nb][bkk][bnn + 4] = rb1;
            __syncthreads();
        }
    }

    // epilogue: scale rows by dis[m]
#pragma unroll
    for (int i = 0; i < 8; i++) {
        int gm = m0 + ty * 8 + i;
        if (gm < M) {
            float s = g_dis[gm];
            float* cp = C + (size_t)gm * N + n0 + tx * 8;
            float4 v0 = {acc[i][0] * s, acc[i][1] * s, acc[i][2] * s, acc[i][3] * s};
            float4 v1 = {acc[i][4] * s, acc[i][5] * s, acc[i][6] * s, acc[i][7] * s};
            *(float4*)(cp)     = v0;
            *(float4*)(cp + 4) = v1;
        }
    }
}

// ----------------------------------------------------------------------------
// pull aggregation + bias + exact GELU
// Out[d,:] = gelu( dis[d] * (Hs[d,:] + sum_{s in N(d)} Hs[s,:]) + bias )
// ----------------------------------------------------------------------------
__device__ __forceinline__ float4 f4add(float4 a, float4 b) {
    return make_float4(a.x + b.x, a.y + b.y, a.z + b.z, a.w + b.w);
}

template <int TPG>
__global__ __launch_bounds__(256)
void agg_gelu_kernel(const float* __restrict__ Hs, const float* __restrict__ bias,
                     float* __restrict__ Out, int n) {
    int gid = (int)(blockIdx.x * blockDim.x + threadIdx.x) / TPG;  // node
    int t   = threadIdx.x & (TPG - 1);                             // float4 slot
    if (gid >= n) return;

    const float4* H4 = (const float4*)Hs;
    int beg = g_rowptr[gid];
    int end = g_rowptr[gid + 1];

    float4 a0 = H4[(size_t)gid * TPG + t];   // self-loop term
    float4 a1 = make_float4(0.f, 0.f, 0.f, 0.f);
    float4 a2 = a1, a3 = a1;

    int p = beg;
    for (; p + 3 < end; p += 4) {
        int s0 = g_col[p];
        int s1 = g_col[p + 1];
        int s2 = g_col[p + 2];
        int s3 = g_col[p + 3];
        a0 = f4add(a0, H4[(size_t)s0 * TPG + t]);
        a1 = f4add(a1, H4[(size_t)s1 * TPG + t]);
        a2 = f4add(a2, H4[(size_t)s2 * TPG + t]);
        a3 = f4add(a3, H4[(size_t)s3 * TPG + t]);
    }
    for (; p < end; p++)
        a0 = f4add(a0, H4[(size_t)g_col[p] * TPG + t]);

    float4 acc = f4add(f4add(a0, a1), f4add(a2, a3));
    float dd = g_dis[gid];
    float4 bb = ((const float4*)bias)[t];

    float x0 = acc.x * dd + bb.x;
    float x1 = acc.y * dd + bb.y;
    float x2 = acc.z * dd + bb.z;
    float x3 = acc.w * dd + bb.w;
    const float inv_sqrt2 = 0.70710678118654752f;
    float4 o;
    o.x = 0.5f * x0 * (1.0f + erff(x0 * inv_sqrt2));
    o.y = 0.5f * x1 * (1.0f + erff(x1 * inv_sqrt2));
    o.z = 0.5f * x2 * (1.0f + erff(x2 * inv_sqrt2));
    o.w = 0.5f * x3 * (1.0f + erff(x3 * inv_sqrt2));
    ((float4*)Out)[(size_t)gid * TPG + t] = o;
}

// ----------------------------------------------------------------------------
extern "C" void kernel_launch(void* const* d_in, const int* in_sizes, int n_in,
                              void* d_out, int out_size) {
    const float* node_emb = (const float*)d_in[0];   // [N, 256]
    const float* W1       = (const float*)d_in[1];   // [256, 256]
    const float* b1       = (const float*)d_in[2];   // [256]
    const float* W2       = (const float*)d_in[3];   // [256, 128]
    const float* b2       = (const float*)d_in[4];   // [128]
    const int*   eidx     = (const int*)d_in[5];     // [2, E]

    int N = in_sizes[0] / EMB;
    int E = in_sizes[5] / 2;
    const int* src = eidx;
    const int* dst = eidx + E;

    float* H1 = nullptr; float* A1 = nullptr; float* H2 = nullptr;
    cudaGetSymbolAddress((void**)&H1, g_H1);
    cudaGetSymbolAddress((void**)&A1, g_A1);
    cudaGetSymbolAddress((void**)&H2, g_H2);
    float* outp = (float*)d_out;

    int nblk_scan = (N + SCAN_B - 1) / SCAN_B;

    // ---- degrees, normalization, CSR ----
    zero_deg_kernel<<<(N + 255) / 256, 256>>>(N);
    count_deg_kernel<<<(E + 255) / 256, 256>>>(dst, E);
    compute_dis_kernel<<<(N + 255) / 256, 256>>>(N);
    scan_phase1_kernel<<<nblk_scan, SCAN_B>>>(N);
    scan_phase2_kernel<<<1, 64>>>(nblk_scan);
    scan_phase3_kernel<<<nblk_scan, SCAN_B>>>(N, nblk_scan);
    fill_csr_kernel<<<(E + 255) / 256, 256>>>(src, dst, E);

    // ---- layer 1: Hs1 = dis .* (node_emb @ W1); A1 = gelu(agg + b1) ----
    {
        dim3 grid(MID / BN, (N + BM - 1) / BM);
        gemm_scale_kernel<<<grid, 256>>>(node_emb, W1, H1, N, MID, EMB);
    }
    {
        const int TPG = MID / 4;  // 64 threads per node
        int groups_per_blk = 256 / TPG;
        int nblk = (N + groups_per_blk - 1) / groups_per_blk;
        agg_gelu_kernel<TPG><<<nblk, 256>>>(H1, b1, A1, N);
    }

    // ---- layer 2: Hs2 = dis .* (A1 @ W2); out = gelu(agg + b2) ----
    {
        dim3 grid(OUTD / BN, (N + BM - 1) / BM);
        gemm_scale_kernel<<<grid, 256>>>(A1, W2, H2, N, OUTD, MID);
    }
    {
        const int TPG = OUTD / 4;  // 32 threads per node
        int groups_per_blk = 256 / TPG;
        int nblk = (N + groups_per_blk - 1) / groups_per_blk;
        agg_gelu_kernel<TPG><<<nblk, 256>>>(H2, b2, outp, N);
    }
}

// round 4
// speedup vs baseline: 1.1632x; 1.1632x over previous
#include <cuda_runtime.h>
#include <math.h>

#define NMAX   50000
#define EMAX   1048576
#define EMB    256
#define MID    256
#define OUTD   128
#define SCAN_B 1024
#define NBLK_SCAN ((NMAX + SCAN_B - 1) / SCAN_B)   // 49

// ---- scratch (static device globals; no runtime allocation) ----
__device__ float g_H1[NMAX * MID];     // dis .* (node_emb @ W1)
__device__ float g_A1[NMAX * MID];     // gelu(agg) -> layer-2 input
__device__ float g_H2[NMAX * OUTD];    // dis .* (A1 @ W2)
__device__ float g_dis[NMAX];          // D^-1/2 (in-degree + self loop)
__device__ int   g_deg[NMAX];
__device__ int   g_rowptr[NMAX + 1];
__device__ int   g_cur[NMAX];
__device__ int   g_col[EMAX];
__device__ int   g_blocksum[NBLK_SCAN + 1];

// ----------------------------------------------------------------------------
// degree / normalization
// ----------------------------------------------------------------------------
__global__ void zero_deg_kernel(int n) {
    int i = blockIdx.x * blockDim.x + threadIdx.x;
    if (i < n) g_deg[i] = 0;
}

__global__ void count_deg_kernel(const int* __restrict__ dst, int E) {
    int e = blockIdx.x * blockDim.x + threadIdx.x;
    if (e < E) atomicAdd(&g_deg[dst[e]], 1);
}

__global__ void compute_dis_kernel(int n) {
    int i = blockIdx.x * blockDim.x + threadIdx.x;
    if (i < n) g_dis[i] = rsqrtf((float)(g_deg[i] + 1));  // +1 = self loop
}

// ----------------------------------------------------------------------------
// multi-block exclusive scan of g_deg -> g_rowptr
// ----------------------------------------------------------------------------
__global__ __launch_bounds__(SCAN_B)
void scan_phase1_kernel(int n) {           // per-block exclusive scan + block sum
    __shared__ int s[SCAN_B];
    int i = blockIdx.x * SCAN_B + threadIdx.x;
    int v = (i < n) ? g_deg[i] : 0;
    s[threadIdx.x] = v;
    __syncthreads();
#pragma unroll
    for (int off = 1; off < SCAN_B; off <<= 1) {
        int t = (threadIdx.x >= off) ? s[threadIdx.x - off] : 0;
        __syncthreads();
        s[threadIdx.x] += t;
        __syncthreads();
    }
    if (i < n) g_rowptr[i] = s[threadIdx.x] - v;   // exclusive, no block offset yet
    if (threadIdx.x == SCAN_B - 1) g_blocksum[blockIdx.x] = s[SCAN_B - 1];
}

__global__ __launch_bounds__(64)
void scan_phase2_kernel(int nblk) {        // exclusive scan of block sums (1 block)
    __shared__ int s[64];
    int v = (threadIdx.x < nblk) ? g_blocksum[threadIdx.x] : 0;
    s[threadIdx.x] = v;
    __syncthreads();
#pragma unroll
    for (int off = 1; off < 64; off <<= 1) {
        int t = (threadIdx.x >= off) ? s[threadIdx.x - off] : 0;
        __syncthreads();
        s[threadIdx.x] += t;
        __syncthreads();
    }
    if (threadIdx.x < nblk) g_blocksum[threadIdx.x] = s[threadIdx.x] - v;
    if (threadIdx.x == 63) g_blocksum[nblk] = s[63];   // total
}

__global__ __launch_bounds__(SCAN_B)
void scan_phase3_kernel(int n, int nblk) { // add offsets, init cursors, tail
    int i = blockIdx.x * SCAN_B + threadIdx.x;
    if (i < n) {
        int ex = g_rowptr[i] + g_blocksum[blockIdx.x];
        g_rowptr[i] = ex;
        g_cur[i] = ex;
    }
    if (i == 0) g_rowptr[n] = g_blocksum[nblk];
}

// ----------------------------------------------------------------------------
// CSR fill: g_col[rowptr[d] + k] = src  (unordered within a segment -- fine)
// ----------------------------------------------------------------------------
__global__ void fill_csr_kernel(const int* __restrict__ src,
                                const int* __restrict__ dst, int E) {
    int e = blockIdx.x * blockDim.x + threadIdx.x;
    if (e < E) {
        int d = dst[e];
        int pos = atomicAdd(&g_cur[d], 1);
        g_col[pos] = src[e];
    }
}

// ----------------------------------------------------------------------------
// fp32 SIMT GEMM with row-scale epilogue:  C[m,:] = dis[m] * (A @ B)[m,:]
// BM=128, BN=64, BK=16, 256 threads, 8x4 per thread. (round-2 known-good)
// ----------------------------------------------------------------------------
#define BM 128
#define BN 64
#define BK 16

__global__ __launch_bounds__(256)
void gemm_scale_kernel(const float* __restrict__ A, const float* __restrict__ B,
                       float* __restrict__ C, int M, int N, int K) {
    __shared__ float As[BK][BM + 4];
    __shared__ float Bs[BK][BN + 4];

    int tid = threadIdx.x;
    int tx = tid & 15;
    int ty = tid >> 4;

    int m0 = blockIdx.y * BM;
    int n0 = blockIdx.x * BN;

    float acc[8][4];
#pragma unroll
    for (int i = 0; i < 8; i++)
#pragma unroll
        for (int j = 0; j < 4; j++) acc[i][j] = 0.0f;

    for (int k0 = 0; k0 < K; k0 += BK) {
        {
            int aRow = tid >> 1;
            int kk8  = (tid & 1) * 8;
            int gm = m0 + aRow;
            if (gm < M) {
                const float* ap = A + (size_t)gm * K + k0 + kk8;
                float4 v0 = *(const float4*)(ap);
                float4 v1 = *(const float4*)(ap + 4);
                As[kk8 + 0][aRow] = v0.x; As[kk8 + 1][aRow] = v0.y;
                As[kk8 + 2][aRow] = v0.z; As[kk8 + 3][aRow] = v0.w;
                As[kk8 + 4][aRow] = v1.x; As[kk8 + 5][aRow] = v1.y;
                As[kk8 + 6][aRow] = v1.z; As[kk8 + 7][aRow] = v1.w;
            } else {
#pragma unroll
                for (int j = 0; j < 8; j++) As[kk8 + j][aRow] = 0.0f;
            }
        }
        {
            int kk = tid >> 4;
            int nn = (tid & 15) * 4;
            float4 v = *(const float4*)(B + (size_t)(k0 + kk) * N + n0 + nn);
            Bs[kk][nn + 0] = v.x; Bs[kk][nn + 1] = v.y;
            Bs[kk][nn + 2] = v.z; Bs[kk][nn + 3] = v.w;
        }
        __syncthreads();

#pragma unroll
        for (int k = 0; k < BK; k++) {
            float4 a0 = *(const float4*)&As[k][ty * 8];
            float4 a1 = *(const float4*)&As[k][ty * 8 + 4];
            float4 b  = *(const float4*)&Bs[k][tx * 4];
            float ar[8] = {a0.x, a0.y, a0.z, a0.w, a1.x, a1.y, a1.z, a1.w};
            float br[4] = {b.x, b.y, b.z, b.w};
#pragma unroll
            for (int i = 0; i < 8; i++)
#pragma unroll
                for (int j = 0; j < 4; j++)
                    acc[i][j] = fmaf(ar[i], br[j], acc[i][j]);
        }
        __syncthreads();
    }

#pragma unroll
    for (int i = 0; i < 8; i++) {
        int gm = m0 + ty * 8 + i;
        if (gm < M) {
            float s = g_dis[gm];
            float4 v = {acc[i][0] * s, acc[i][1] * s, acc[i][2] * s, acc[i][3] * s};
            *(float4*)(C + (size_t)gm * N + n0 + tx * 4) = v;
        }
    }
}

// ----------------------------------------------------------------------------
// pull aggregation + bias + exact GELU
// Out[d,:] = gelu( dis[d] * (Hs[d,:] + sum_{s in N(d)} Hs[s,:]) + bias )
// ----------------------------------------------------------------------------
__device__ __forceinline__ float4 f4add(float4 a, float4 b) {
    return make_float4(a.x + b.x, a.y + b.y, a.z + b.z, a.w + b.w);
}

template <int TPG>
__global__ __launch_bounds__(256)
void agg_gelu_kernel(const float* __restrict__ Hs, const float* __restrict__ bias,
                     float* __restrict__ Out, int n) {
    int gid = (int)(blockIdx.x * blockDim.x + threadIdx.x) / TPG;  // node
    int t   = threadIdx.x & (TPG - 1);                             // float4 slot
    if (gid >= n) return;

    const float4* H4 = (const float4*)Hs;
    int beg = g_rowptr[gid];
    int end = g_rowptr[gid + 1];

    float4 a0 = H4[(size_t)gid * TPG + t];   // self-loop term
    float4 a1 = make_float4(0.f, 0.f, 0.f, 0.f);
    float4 a2 = a1, a3 = a1;

    int p = beg;
    for (; p + 3 < end; p += 4) {
        int s0 = g_col[p];
        int s1 = g_col[p + 1];
        int s2 = g_col[p + 2];
        int s3 = g_col[p + 3];
        a0 = f4add(a0, H4[(size_t)s0 * TPG + t]);
        a1 = f4add(a1, H4[(size_t)s1 * TPG + t]);
        a2 = f4add(a2, H4[(size_t)s2 * TPG + t]);
        a3 = f4add(a3, H4[(size_t)s3 * TPG + t]);
    }
    for (; p < end; p++)
        a0 = f4add(a0, H4[(size_t)g_col[p] * TPG + t]);

    float4 acc = f4add(f4add(a0, a1), f4add(a2, a3));
    float dd = g_dis[gid];
    float4 bb = ((const float4*)bias)[t];

    float x0 = acc.x * dd + bb.x;
    float x1 = acc.y * dd + bb.y;
    float x2 = acc.z * dd + bb.z;
    float x3 = acc.w * dd + bb.w;
    const float inv_sqrt2 = 0.70710678118654752f;
    float4 o;
    o.x = 0.5f * x0 * (1.0f + erff(x0 * inv_sqrt2));
    o.y = 0.5f * x1 * (1.0f + erff(x1 * inv_sqrt2));
    o.z = 0.5f * x2 * (1.0f + erff(x2 * inv_sqrt2));
    o.w = 0.5f * x3 * (1.0f + erff(x3 * inv_sqrt2));
    ((float4*)Out)[(size_t)gid * TPG + t] = o;
}

// ----------------------------------------------------------------------------
extern "C" void kernel_launch(void* const* d_in, const int* in_sizes, int n_in,
                              void* d_out, int out_size) {
    const float* node_emb = (const float*)d_in[0];   // [N, 256]
    const float* W1       = (const float*)d_in[1];   // [256, 256]
    const float* b1       = (const float*)d_in[2];   // [256]
    const float* W2       = (const float*)d_in[3];   // [256, 128]
    const float* b2       = (const float*)d_in[4];   // [128]
    const int*   eidx     = (const int*)d_in[5];     // [2, E]

    int N = in_sizes[0] / EMB;
    int E = in_sizes[5] / 2;
    const int* src = eidx;
    const int* dst = eidx + E;

    float* H1 = nullptr; float* A1 = nullptr; float* H2 = nullptr;
    cudaGetSymbolAddress((void**)&H1, g_H1);
    cudaGetSymbolAddress((void**)&A1, g_A1);
    cudaGetSymbolAddress((void**)&H2, g_H2);
    float* outp = (float*)d_out;

    int nblk_scan = (N + SCAN_B - 1) / SCAN_B;

    // ---- degrees, normalization, CSR ----
    zero_deg_kernel<<<(N + 255) / 256, 256>>>(N);
    count_deg_kernel<<<(E + 255) / 256, 256>>>(dst, E);
    compute_dis_kernel<<<(N + 255) / 256, 256>>>(N);
    scan_phase1_kernel<<<nblk_scan, SCAN_B>>>(N);
    scan_phase2_kernel<<<1, 64>>>(nblk_scan);
    scan_phase3_kernel<<<nblk_scan, SCAN_B>>>(N, nblk_scan);
    fill_csr_kernel<<<(E + 255) / 256, 256>>>(src, dst, E);

    // ---- layer 1: Hs1 = dis .* (node_emb @ W1); A1 = gelu(agg + b1) ----
    {
        dim3 grid(MID / BN, (N + BM - 1) / BM);
        gemm_scale_kernel<<<grid, 256>>>(node_emb, W1, H1, N, MID, EMB);
    }
    {
        const int TPG = MID / 4;  // 64 threads per node
        int groups_per_blk = 256 / TPG;
        int nblk = (N + groups_per_blk - 1) / groups_per_blk;
        agg_gelu_kernel<TPG><<<nblk, 256>>>(H1, b1, A1, N);
    }

    // ---- layer 2: Hs2 = dis .* (A1 @ W2); out = gelu(agg + b2) ----
    {
        dim3 grid(OUTD / BN, (N + BM - 1) / BM);
        gemm_scale_kernel<<<grid, 256>>>(A1, W2, H2, N, OUTD, MID);
    }
    {
        const int TPG = OUTD / 4;  // 32 threads per node
        int groups_per_blk = 256 / TPG;
        int nblk = (N + groups_per_blk - 1) / groups_per_blk;
        agg_gelu_kernel<TPG><<<nblk, 256>>>(H2, b2, outp, N);
    }
}